// round 10
// baseline (speedup 1.0000x reference)
#include <cuda_runtime.h>
#include <cuda_bf16.h>

#define N_ROWS 16384
#define N_COLS 4096
#define MARGIN 0.1f
#define THREADS 256
#define GRID 512
#define NWARP (THREADS / 32)
#define WARPS_TOTAL (GRID * NWARP)            // 4096
#define ROWS_PER_WARP (N_ROWS / WARPS_TOTAL)  // 4
#define GRAN_PER_LANE (N_COLS / 4 / 32)       // 32 granules per lane per row

// Scratch (device globals: no allocation).
__device__ float g_partial[WARPS_TOTAL];
__device__ unsigned int g_count = 0;

__global__ void __launch_bounds__(THREADS, 4) mm_warp2_kernel(
    const float* __restrict__ cossim,
    const int* __restrict__ target,
    float* __restrict__ out)
{
    const int t    = threadIdx.x;
    const int lane = t & 31;
    const int wid  = t >> 5;
    const int gw   = blockIdx.x * NWARP + wid;   // global warp id

    float acc = 0.0f;

#pragma unroll 1                       // CRITICAL: do not interleave rows (R3 bug)
    for (int r = 0; r < ROWS_PER_WARP; r++) {
        const int row = gw + r * WARPS_TOTAL;
        const int4* __restrict__ trow =
            reinterpret_cast<const int4*>(target + (size_t)row * N_COLS);
        const float4* __restrict__ crow =
            reinterpret_cast<const float4*>(cossim + (size_t)row * N_COLS);

        // ---- Pass 1: scan target (4 batches of 8 int4) ----
        int jcol = 0;
        bool found = false;
#pragma unroll
        for (int b = 0; b < GRAN_PER_LANE / 8; b++) {
            int4 v[8];
#pragma unroll
            for (int i = 0; i < 8; i++)
                v[i] = __ldcs(&trow[(b * 8 + i) * 32 + lane]);
#pragma unroll
            for (int i = 0; i < 8; i++) {
                const int g = (b * 8 + i) * 32 + lane;
                if (v[i].x == 1) { jcol = g * 4 + 0; found = true; }
                if (v[i].y == 1) { jcol = g * 4 + 1; found = true; }
                if (v[i].z == 1) { jcol = g * 4 + 2; found = true; }
                if (v[i].w == 1) { jcol = g * 4 + 3; found = true; }
            }
        }

        // Warp-local broadcast of correct-class value (no block barrier).
        const unsigned m = __ballot_sync(0xffffffffu, found);
        const int src = __ffs(m) - 1;
        float corr_l = 0.0f;
        if (found)
            corr_l = __ldg(&cossim[(size_t)row * N_COLS + jcol]);
        const float corr = __shfl_sync(0xffffffffu, corr_l, src);

        // ---- Pass 2: stream cossim (4 batches of 8 float4), hinge sum ----
        // (correct column contributes exactly MARGIN; removed once per row)
        float sum = 0.0f;
#pragma unroll
        for (int b = 0; b < GRAN_PER_LANE / 8; b++) {
            float4 c[8];
#pragma unroll
            for (int i = 0; i < 8; i++)
                c[i] = __ldcs(&crow[(b * 8 + i) * 32 + lane]);
#pragma unroll
            for (int i = 0; i < 8; i++) {
                sum += fmaxf(MARGIN + c[i].x - corr, 0.0f);
                sum += fmaxf(MARGIN + c[i].y - corr, 0.0f);
                sum += fmaxf(MARGIN + c[i].z - corr, 0.0f);
                sum += fmaxf(MARGIN + c[i].w - corr, 0.0f);
            }
        }
        acc += sum;
    }

    // Warp reduce; lane 0 publishes this warp's partial.
#pragma unroll
    for (int off = 16; off > 0; off >>= 1)
        acc += __shfl_down_sync(0xffffffffu, acc, off);
    if (lane == 0)
        g_partial[gw] = acc - (float)ROWS_PER_WARP * MARGIN;

    // ---- Ticket: last CTA does the deterministic final reduction ----
    __shared__ unsigned int s_ticket;
    __shared__ float s_warp[NWARP];
    __syncthreads();
    if (t == 0) {
        __threadfence();
        s_ticket = atomicAdd(&g_count, 1u);
    }
    __syncthreads();

    if (s_ticket == (unsigned int)(GRID - 1)) {
        __threadfence();

        const float4* __restrict__ p4 = reinterpret_cast<const float4*>(g_partial);
        float s = 0.0f;
#pragma unroll
        for (int k = 0; k < (WARPS_TOTAL / 4) / THREADS; k++) {  // 4 granules/thread
            float4 v = __ldcg(&p4[k * THREADS + t]);
            s += v.x + v.y + v.z + v.w;
        }

#pragma unroll
        for (int off = 16; off > 0; off >>= 1)
            s += __shfl_down_sync(0xffffffffu, s, off);
        if (lane == 0) s_warp[wid] = s;
        __syncthreads();

        if (t == 0) {
            float v = s_warp[0];
#pragma unroll
            for (int w = 1; w < NWARP; w++) v += s_warp[w];
            out[0] = v * (1.0f / (float)N_ROWS);
            g_count = 0;   // reset for next graph replay
        }
    }
}

extern "C" void kernel_launch(void* const* d_in, const int* in_sizes, int n_in,
                              void* d_out, int out_size)
{
    const float* cossim = (const float*)d_in[0];
    const int*   target = (const int*)d_in[1];
    float* out = (float*)d_out;

    mm_warp2_kernel<<<GRID, THREADS>>>(cossim, target, out);
}

// round 11
// speedup vs baseline: 1.3766x; 1.3766x over previous
#include <cuda_runtime.h>
#include <cstdint>
#include <cstddef>

#define N_ROWS 16384
#define N_COLS 4096
#define MARGIN 0.1f
#define THREADS 256
#define GRID 444                     // 3 CTAs/SM x 148 SMs, single resident wave
#define NWARP (THREADS / 32)
#define SLOT_BYTES (N_COLS * 4)      // 16 KB per array per slot
#define DYN_SMEM (4 * SLOT_BYTES)    // 2 slots x (cossim + target) = 64 KB

// Scratch (device globals: no allocation).
__device__ float g_partial[GRID];
__device__ unsigned int g_count = 0;

__device__ __forceinline__ uint32_t smem_u32(const void* p) {
    uint32_t a;
    asm("{ .reg .u64 t; cvta.to.shared.u64 t, %1; cvt.u32.u64 %0, t; }"
        : "=r"(a) : "l"(p));
    return a;
}

#define WAIT_PARITY(mb, ph)                                                   \
    asm volatile(                                                             \
        "{\n\t.reg .pred P;\n\t"                                              \
        "WL_%=:\n\t"                                                          \
        "mbarrier.try_wait.parity.acquire.cta.shared::cta.b64 P, [%0], %1, 0x989680;\n\t" \
        "@P bra.uni WD_%=;\n\t"                                               \
        "bra.uni WL_%=;\n\t"                                                  \
        "WD_%=:\n\t}"                                                         \
        :: "r"(mb), "r"(ph) : "memory")

extern __shared__ char dynsmem[];

__global__ void __launch_bounds__(THREADS) mm_bulk_kernel(
    const float* __restrict__ cossim,
    const int* __restrict__ target,
    float* __restrict__ out)
{
    const int bid  = blockIdx.x;
    const int t    = threadIdx.x;
    const int lane = t & 31;
    const int wid  = t >> 5;

    // smem layout: [cossim s0][cossim s1][target s0][target s1]
    float* s_cos[2] = { (float*)(dynsmem),
                        (float*)(dynsmem + SLOT_BYTES) };
    int*   s_tgt[2] = { (int*)(dynsmem + 2 * SLOT_BYTES),
                        (int*)(dynsmem + 3 * SLOT_BYTES) };

    __shared__ alignas(8) unsigned long long mbar[2];
    __shared__ float s_corr;
    __shared__ float s_warp[NWARP];
    __shared__ unsigned int s_ticket;

    const int nrows = (N_ROWS - bid + GRID - 1) / GRID;   // 36 or 37

    uint32_t mb[2];
    if (t == 0) {
        mb[0] = smem_u32(&mbar[0]);
        mb[1] = smem_u32(&mbar[1]);
        asm volatile("mbarrier.init.shared.b64 [%0], 1;" :: "r"(mb[0]));
        asm volatile("mbarrier.init.shared.b64 [%0], 1;" :: "r"(mb[1]));
        asm volatile("fence.proxy.async.shared::cta;" ::: "memory");

        // Prologue: issue rows bid (slot 0) and bid+GRID (slot 1).
#pragma unroll
        for (int s = 0; s < 2; s++) {
            const int row = bid + s * GRID;              // always < N_ROWS
            asm volatile("mbarrier.arrive.expect_tx.shared.b64 _, [%0], %1;"
                         :: "r"(mb[s]), "r"(2 * SLOT_BYTES) : "memory");
            const char* gc = (const char*)(cossim + (size_t)row * N_COLS);
            const char* gt = (const char*)(target + (size_t)row * N_COLS);
            asm volatile(
                "cp.async.bulk.shared::cluster.global.mbarrier::complete_tx::bytes [%0], [%1], %2, [%3];"
                :: "r"(smem_u32(s_cos[s])), "l"(gc), "r"(SLOT_BYTES), "r"(mb[s]) : "memory");
            asm volatile(
                "cp.async.bulk.shared::cluster.global.mbarrier::complete_tx::bytes [%0], [%1], %2, [%3];"
                :: "r"(smem_u32(s_tgt[s])), "l"(gt), "r"(SLOT_BYTES), "r"(mb[s]) : "memory");
        }
    }
    __syncthreads();

    float acc = 0.0f;

#pragma unroll 1
    for (int it = 0; it < nrows; it++) {
        const int slot = it & 1;
        const int ph   = (it >> 1) & 1;    // per-slot completion parity

        // Wait for this slot's fill (tid0 polls; bar.sync propagates).
        if (t == 0) WAIT_PARITY(mb[slot], ph);
        __syncthreads();                   // B1: data visible

        // Load this thread's 16 ints + 16 floats from smem.
        const int4*   tp = (const int4*)s_tgt[slot];
        const float4* cp = (const float4*)s_cos[slot];
        int4   tv[4];
        float4 c[4];
#pragma unroll
        for (int k = 0; k < 4; k++) tv[k] = tp[k * THREADS + t];
#pragma unroll
        for (int k = 0; k < 4; k++) c[k]  = cp[k * THREADS + t];

        // Scan: exactly one thread holds the one-hot column.
        float corr_local = 0.0f;
        bool found = false;
#pragma unroll
        for (int k = 0; k < 4; k++) {
            if (tv[k].x == 1) { corr_local = c[k].x; found = true; }
            if (tv[k].y == 1) { corr_local = c[k].y; found = true; }
            if (tv[k].z == 1) { corr_local = c[k].z; found = true; }
            if (tv[k].w == 1) { corr_local = c[k].w; found = true; }
        }
        if (found) s_corr = corr_local;
        __syncthreads();                   // B2: corr ready; all LDS retired
        const float corr = s_corr;

        // Refill this slot with row + 2*GRID (producer decoupled from hinge).
        const int rn = bid + (it + 2) * GRID;
        if (t == 0 && rn < N_ROWS) {
            asm volatile("fence.proxy.async.shared::cta;" ::: "memory");
            asm volatile("mbarrier.arrive.expect_tx.shared.b64 _, [%0], %1;"
                         :: "r"(mb[slot]), "r"(2 * SLOT_BYTES) : "memory");
            const char* gc = (const char*)(cossim + (size_t)rn * N_COLS);
            const char* gt = (const char*)(target + (size_t)rn * N_COLS);
            asm volatile(
                "cp.async.bulk.shared::cluster.global.mbarrier::complete_tx::bytes [%0], [%1], %2, [%3];"
                :: "r"(smem_u32(s_cos[slot])), "l"(gc), "r"(SLOT_BYTES), "r"(mb[slot]) : "memory");
            asm volatile(
                "cp.async.bulk.shared::cluster.global.mbarrier::complete_tx::bytes [%0], [%1], %2, [%3];"
                :: "r"(smem_u32(s_tgt[slot])), "l"(gt), "r"(SLOT_BYTES), "r"(mb[slot]) : "memory");
        }

        // Hinge on register-held cossim (correct column contributes exactly
        // MARGIN; removed per-CTA at the end).
        float sum = 0.0f;
#pragma unroll
        for (int k = 0; k < 4; k++) {
            sum += fmaxf(MARGIN + c[k].x - corr, 0.0f);
            sum += fmaxf(MARGIN + c[k].y - corr, 0.0f);
            sum += fmaxf(MARGIN + c[k].z - corr, 0.0f);
            sum += fmaxf(MARGIN + c[k].w - corr, 0.0f);
        }
        acc += sum;
    }

    // ---- Block reduce per-CTA accumulator ----
#pragma unroll
    for (int off = 16; off > 0; off >>= 1)
        acc += __shfl_down_sync(0xffffffffu, acc, off);
    if (lane == 0) s_warp[wid] = acc;
    __syncthreads();

    if (t == 0) {
        float v = s_warp[0];
#pragma unroll
        for (int w = 1; w < NWARP; w++) v += s_warp[w];
        g_partial[bid] = v - (float)nrows * MARGIN;
        __threadfence();
        s_ticket = atomicAdd(&g_count, 1u);
    }
    __syncthreads();

    // ---- Last CTA: deterministic final reduction of GRID partials ----
    if (s_ticket == (unsigned int)(GRID - 1)) {
        __threadfence();

        float s = 0.0f;
        for (int i = t; i < GRID; i += THREADS)
            s += __ldcg(&g_partial[i]);

#pragma unroll
        for (int off = 16; off > 0; off >>= 1)
            s += __shfl_down_sync(0xffffffffu, s, off);
        if (lane == 0) s_warp[wid] = s;
        __syncthreads();

        if (t == 0) {
            float v = s_warp[0];
#pragma unroll
            for (int w = 1; w < NWARP; w++) v += s_warp[w];
            out[0] = v * (1.0f / (float)N_ROWS);
            g_count = 0;   // reset for next graph replay
        }
    }
}

extern "C" void kernel_launch(void* const* d_in, const int* in_sizes, int n_in,
                              void* d_out, int out_size)
{
    const float* cossim = (const float*)d_in[0];
    const int*   target = (const int*)d_in[1];
    float* out = (float*)d_out;

    cudaFuncSetAttribute(mm_bulk_kernel,
                         cudaFuncAttributeMaxDynamicSharedMemorySize, DYN_SMEM);
    mm_bulk_kernel<<<GRID, THREADS, DYN_SMEM>>>(cossim, target, out);
}

// round 16
// speedup vs baseline: 1.5410x; 1.1194x over previous
#include <cuda_runtime.h>
#include <cuda_bf16.h>

#define N_ROWS 16384
#define N_COLS 4096
#define MARGIN 0.1f
#define THREADS 256
#define GRID 512
#define ROWS_PER_CTA (N_ROWS / GRID)   // 32, exact
#define NWARP (THREADS / 32)

// Scratch (device globals: no allocation).
__device__ float g_partial[GRID];
__device__ unsigned int g_count = 0;

__global__ void __launch_bounds__(THREADS, 4) mm_pipe_kernel(
    const float* __restrict__ cossim,
    const int* __restrict__ target,
    float* __restrict__ out)
{
    const int bid  = blockIdx.x;
    const int t    = threadIdx.x;
    const int lane = t & 31;
    const int wid  = t >> 5;

    __shared__ float s_corr[2];
    __shared__ float s_warp[NWARP];
    __shared__ unsigned int s_ticket;

    // ---- Preload first row (row = bid) ----
    float4 c[4];
    int4   tv[4];
    {
        const float4* __restrict__ crow =
            reinterpret_cast<const float4*>(cossim + (size_t)bid * N_COLS);
        const int4* __restrict__ trow =
            reinterpret_cast<const int4*>(target + (size_t)bid * N_COLS);
#pragma unroll
        for (int k = 0; k < 4; k++) c[k]  = __ldcs(&crow[k * THREADS + t]);
#pragma unroll
        for (int k = 0; k < 4; k++) tv[k] = __ldcs(&trow[k * THREADS + t]);
    }

    float acc = 0.0f;
    int par = 0;

#pragma unroll 1
    for (int r = bid; r < N_ROWS; r += GRID, par ^= 1) {
        // ---- 1) Scan current target regs (ALU only; tv dies here) ----
        float corr_local = 0.0f;
        bool found = false;
#pragma unroll
        for (int k = 0; k < 4; k++) {
            if (tv[k].x == 1) { corr_local = c[k].x; found = true; }
            if (tv[k].y == 1) { corr_local = c[k].y; found = true; }
            if (tv[k].z == 1) { corr_local = c[k].z; found = true; }
            if (tv[k].w == 1) { corr_local = c[k].w; found = true; }
        }

        // ---- 2) Issue NEXT row's loads (in flight across barrier+compute) ----
        float4 cn[4];
        int4   tn[4];
        const int rn = r + GRID;
        if (rn < N_ROWS) {
            const float4* __restrict__ crow =
                reinterpret_cast<const float4*>(cossim + (size_t)rn * N_COLS);
            const int4* __restrict__ trow =
                reinterpret_cast<const int4*>(target + (size_t)rn * N_COLS);
#pragma unroll
            for (int k = 0; k < 4; k++) cn[k] = __ldcs(&crow[k * THREADS + t]);
#pragma unroll
            for (int k = 0; k < 4; k++) tn[k] = __ldcs(&trow[k * THREADS + t]);
        }

        // ---- 3) Broadcast corr (parity double-buffered, one barrier) ----
        if (found) s_corr[par] = corr_local;
        __syncthreads();
        const float corr = s_corr[par];

        // ---- 4) Hinge on current row's register-held cossim ----
        // (correct column contributes exactly MARGIN; removed per-CTA at end)
        float sum = 0.0f;
#pragma unroll
        for (int k = 0; k < 4; k++) {
            sum += fmaxf(MARGIN + c[k].x - corr, 0.0f);
            sum += fmaxf(MARGIN + c[k].y - corr, 0.0f);
            sum += fmaxf(MARGIN + c[k].z - corr, 0.0f);
            sum += fmaxf(MARGIN + c[k].w - corr, 0.0f);
        }
        acc += sum;

        // ---- 5) Rotate pipeline ----
#pragma unroll
        for (int k = 0; k < 4; k++) { c[k] = cn[k]; tv[k] = tn[k]; }
    }

    // ---- Block reduce per-CTA accumulator ----
#pragma unroll
    for (int off = 16; off > 0; off >>= 1)
        acc += __shfl_down_sync(0xffffffffu, acc, off);
    if (lane == 0) s_warp[wid] = acc;
    __syncthreads();

    if (t == 0) {
        float v = s_warp[0];
#pragma unroll
        for (int w = 1; w < NWARP; w++) v += s_warp[w];
        g_partial[bid] = v - (float)ROWS_PER_CTA * MARGIN;
        __threadfence();
        s_ticket = atomicAdd(&g_count, 1u);
    }
    __syncthreads();

    // ---- Last CTA: deterministic final reduction of 512 partials ----
    if (s_ticket == (unsigned int)(GRID - 1)) {
        __threadfence();

        float s = __ldcg(&g_partial[t]) + __ldcg(&g_partial[THREADS + t]);

#pragma unroll
        for (int off = 16; off > 0; off >>= 1)
            s += __shfl_down_sync(0xffffffffu, s, off);
        if (lane == 0) s_warp[wid] = s;
        __syncthreads();

        if (t == 0) {
            float v = s_warp[0];
#pragma unroll
            for (int w = 1; w < NWARP; w++) v += s_warp[w];
            out[0] = v * (1.0f / (float)N_ROWS);
            g_count = 0;   // reset for next graph replay
        }
    }
}

extern "C" void kernel_launch(void* const* d_in, const int* in_sizes, int n_in,
                              void* d_out, int out_size)
{
    const float* cossim = (const float*)d_in[0];
    const int*   target = (const int*)d_in[1];
    float* out = (float*)d_out;

    mm_pipe_kernel<<<GRID, THREADS>>>(cossim, target, out);
}